// round 15
// baseline (speedup 1.0000x reference)
#include <cuda_runtime.h>
#include <cstddef>

#define Hd    50
#define WP    52          // staged row stride (floats)
#define G4    200
#define Bsz   4096
#define Tt    256
#define TBtot (Tt*Bsz)    // 1048576
#define CHK   24          // xgemm chunk (elements)
#define NCHK  43691       // ceil(TBtot/24)
#define TBP   ((size_t)NCHK * CHK)   // 1048584 padded tb extent
#define RNT   384         // rec threads (12 warps = 3 groups x 4 warps)
#define EPG   10          // rec: elements per group
#define EPCTA 30          // rec: elements per CTA (3 groups)
#define RGRID ((Bsz + EPCTA - 1) / EPCTA)   // 137 CTAs

typedef unsigned long long ull;

// Inter-layer activations [tb][50] + input-side preacts [tb][200], padded to TBP
__device__ float g_ysA[TBP * Hd];
__device__ float g_ysB[TBP * Hd];
__device__ float g_xg[TBP * 200];

__device__ __forceinline__ ull ffma2(ull a, ull b, ull c) {
    ull d;
    asm("fma.rn.f32x2 %0, %1, %2, %3;" : "=l"(d) : "l"(a), "l"(b), "l"(c));
    return d;
}
__device__ __forceinline__ float f2sum(ull v) {
    float lo, hi;
    asm("mov.b64 {%0, %1}, %2;" : "=f"(lo), "=f"(hi) : "l"(v));
    return lo + hi;
}
__device__ __forceinline__ float sigf(float x) {
    return __fdividef(1.0f, 1.0f + __expf(-x));
}
__device__ __forceinline__ float tanhf_fast(float x) {
    return 1.0f - __fdividef(2.0f, __expf(2.0f * x) + 1.0f);
}

// ---------------- Phase A, layer 0: XG = x * w_ih0^T + b0 (rank-1) -------------
__global__ __launch_bounds__(200) void xg0_kernel(const float* __restrict__ x,
                                                  const float* __restrict__ w0,
                                                  const float* __restrict__ b0)
{
    __shared__ float xs[32];
    const int cid = blockIdx.x;
    const int t   = cid >> 7;
    const int bb  = (cid & 127) << 5;
    const int row = threadIdx.x;           // 0..199
    if (row < 32) xs[row] = x[(size_t)(bb + row) * Tt + t];
    const float wv = w0[row], bv = b0[row];
    __syncthreads();
    float* base = g_xg + ((size_t)t * Bsz + bb) * 200 + row;
    #pragma unroll 8
    for (int el = 0; el < 32; el++)
        base[(size_t)el * 200] = xs[el] * wv + bv;
}

// ---------------- Phase A, layers 1..4: XG = ys * W_ih^T + bias ----------------
// 384 threads = 3 teams x 4 warps; warp owns TWO row-sets (rA=50wg+lane, rB=rA+25,
// 100 weight regs). Team tm handles 8 els of the 24-el chunk; h loaded once per
// el, reused for both row-sets -> broadcast LDS halved. Warp el-order rotated
// by wg*2 to break LDS/FMA convoys.
__global__ __launch_bounds__(RNT, 1) void xgemm_kernel(const float* __restrict__ ys,
                                                       const float* __restrict__ w,
                                                       const float* __restrict__ bias)
{
    __shared__ float sin[CHK * WP];
    const int tid  = threadIdx.x;
    const int wid  = tid >> 5;
    const int lane = tid & 31;
    const int tm   = wid >> 2;          // team 0..2
    const int wg   = wid & 3;           // warp-in-team 0..3
    const bool act = lane < 25;
    const int rA   = 50 * wg + (act ? lane : 24);
    const int rB   = rA + 25;
    const int eb   = tm * 8;            // team's el base

    ull wregA[25], wregB[25];
    {
        const ull* wpA = (const ull*)(w + rA * Hd);
        const ull* wpB = (const ull*)(w + rB * Hd);
        #pragma unroll
        for (int q = 0; q < 25; q++) { wregA[q] = wpA[q]; wregB[q] = wpB[q]; }
    }
    const float brA = bias[rA], brB = bias[rB];

    int c = blockIdx.x;
    float pf[4];
    #pragma unroll
    for (int k = 0; k < 4; k++) {
        int idx = tid + RNT * k;
        pf[k] = (idx < CHK * Hd) ? ys[(size_t)c * (CHK * Hd) + idx] : 0.0f;
    }

    for (; c < NCHK; c += gridDim.x) {
        __syncthreads();
        #pragma unroll
        for (int k = 0; k < 4; k++) {
            int idx = tid + RNT * k;
            if (idx < CHK * Hd) { int el = idx / Hd, j = idx - el * Hd; sin[el * WP + j] = pf[k]; }
        }
        __syncthreads();
        int cn = c + gridDim.x;
        if (cn < NCHK) {
            #pragma unroll
            for (int k = 0; k < 4; k++) {
                int idx = tid + RNT * k;
                if (idx < CHK * Hd) pf[k] = ys[(size_t)cn * (CHK * Hd) + idx];
            }
        }
        float* obase = g_xg + ((size_t)c * CHK + eb) * 200;

        #pragma unroll
        for (int k = 0; k < 8; k++) {
            const int el = (k + wg * 2) & 7;   // rotated visit order
            const ulonglong2* hp = (const ulonglong2*)(sin + (eb + el) * WP);
            ulonglong2 hv[13];
            #pragma unroll
            for (int q = 0; q < 13; q++) hv[q] = hp[q];
            ull accA = 0ull, accB = 0ull;
            #pragma unroll
            for (int q = 0; q < 12; q++) {
                accA = ffma2(wregA[2*q],   hv[q].x, accA);
                accA = ffma2(wregA[2*q+1], hv[q].y, accA);
                accB = ffma2(wregB[2*q],   hv[q].x, accB);
                accB = ffma2(wregB[2*q+1], hv[q].y, accB);
            }
            accA = ffma2(wregA[24], hv[12].x, accA);   // floats 48,49 (pads excluded)
            accB = ffma2(wregB[24], hv[12].x, accB);
            if (act) {
                obase[(size_t)el * 200 + rA] = f2sum(accA) + brA;
                obase[(size_t)el * 200 + rB] = f2sum(accB) + brB;
            }
        }
    }
}

// ---------------- Phase B: recurrence, weights register-stationary -------------
// 12 warps = 3 groups x 4 warps; group owns EPG=10 batch elements (CTA=30).
// Warp owns TWO row-sets; h loaded once per element for both. Warp el-order
// rotated by wg*3 to break LDS/FMA convoys.
__global__ __launch_bounds__(RNT, 1)
void rec_kernel(const float* __restrict__ w_hh,
                float* __restrict__ ys_out,
                const float* __restrict__ fc_w,
                const float* __restrict__ fc_b,
                float* __restrict__ out)
{
    __shared__ float hbuf[EPCTA][52];    // [ei][u], cols 50,51 stay 0
    __shared__ float pbuf[EPCTA][208];   // [ei][row]

    const int tid  = threadIdx.x;
    const int wid  = tid >> 5;
    const int lane = tid & 31;
    const int g    = wid >> 2;        // group 0..2
    const int wg   = wid & 3;         // warp-in-group 0..3
    const int tidg = tid & 127;       // thread-in-group (128 per group)
    const int barid = 1 + g;

    const int bG = blockIdx.x * EPCTA + g * EPG;   // group's first element

    // ---- weights: lane<25 owns rows rA=50wg+lane and rB=rA+25 ----
    const bool wact = lane < 25;
    const int rA = 50 * wg + (wact ? lane : 24);
    const int rB = rA + 25;
    ull wregA[25], wregB[25];
    {
        const ull* wpA = (const ull*)(w_hh + rA * Hd);
        const ull* wpB = (const ull*)(w_hh + rB * Hd);
        #pragma unroll
        for (int q = 0; q < 25; q++) { wregA[q] = wpA[q]; wregB[q] = wpB[q]; }
    }

    // ---- gates items: 4 fixed (el,u) per thread (500 items over 128 threads) ----
    int elk[4], uk[4];
    bool actk[4], gbl[4];
    #pragma unroll
    for (int k = 0; k < 4; k++) {
        int item = tidg + 128 * k;
        actk[k] = item < EPG * 50;
        int it = actk[k] ? item : (EPG * 50 - 1);
        elk[k] = it / 50;
        uk[k]  = it - elk[k] * 50;
        gbl[k] = actk[k] && (bG + elk[k] < Bsz);
    }
    float c[4] = {0.f, 0.f, 0.f, 0.f};

    // ---- zero hbuf ----
    for (int i = tid; i < EPCTA * 52; i += RNT) ((float*)hbuf)[i] = 0.0f;
    __syncthreads();

    for (int t = 0; t < Tt; t++) {
        const size_t tb = (size_t)t * Bsz;

        // ---- XG prefetch for my gate items (guarded, hidden under dot) ----
        float xgr[4][4];
        #pragma unroll
        for (int k = 0; k < 4; k++) {
            if (gbl[k]) {
                const float* xp = g_xg + (tb + bG + elk[k]) * 200 + uk[k];
                #pragma unroll
                for (int gg = 0; gg < 4; gg++) xgr[k][gg] = xp[gg * 50];
            } else {
                #pragma unroll
                for (int gg = 0; gg < 4; gg++) xgr[k][gg] = 0.0f;
            }
        }

        // ---- dot: EPG elements in rotated order; h loaded once per el ----
        #pragma unroll
        for (int k = 0; k < EPG; k++) {
            int el = k + wg * 3;
            if (el >= EPG) el -= EPG;      // rotated visit order
            const int ei = g * EPG + el;
            ulonglong2 hv[13];
            {
                const ulonglong2* hp = (const ulonglong2*)hbuf[ei];
                #pragma unroll
                for (int q = 0; q < 13; q++) hv[q] = hp[q];
            }
            ull accA = 0ull, accB = 0ull;
            #pragma unroll
            for (int q = 0; q < 12; q++) {
                accA = ffma2(wregA[2*q],   hv[q].x, accA);
                accA = ffma2(wregA[2*q+1], hv[q].y, accA);
                accB = ffma2(wregB[2*q],   hv[q].x, accB);
                accB = ffma2(wregB[2*q+1], hv[q].y, accB);
            }
            accA = ffma2(wregA[24], hv[12].x, accA);
            accB = ffma2(wregB[24], hv[12].x, accB);
            if (wact) {
                pbuf[ei][rA] = f2sum(accA);
                pbuf[ei][rB] = f2sum(accB);
            }
        }

        asm volatile("bar.sync %0, %1;" :: "r"(barid), "r"(128) : "memory");

        // ---- gates: 500 items over 128 group threads ----
        #pragma unroll
        for (int k = 0; k < 4; k++) {
            if (actk[k]) {
                const int ei = g * EPG + elk[k];
                const int u  = uk[k];
                float pi = pbuf[ei][u]        + xgr[k][0];
                float pf = pbuf[ei][50 + u]   + xgr[k][1];
                float pg = pbuf[ei][100 + u]  + xgr[k][2];
                float po = pbuf[ei][150 + u]  + xgr[k][3];
                c[k] = sigf(pf) * c[k] + sigf(pi) * tanhf_fast(pg);
                float hv = sigf(po) * tanhf_fast(c[k]);
                hbuf[ei][u] = hv;
                if (gbl[k] && ys_out) ys_out[(tb + bG + elk[k]) * Hd + u] = hv;
            }
        }

        asm volatile("bar.sync %0, %1;" :: "r"(barid), "r"(128) : "memory");
    }

    // ---- FC head (last layer only) ----
    if (out != nullptr) {
        __syncthreads();
        int be = blockIdx.x * EPCTA + tid;
        if (tid < EPCTA && be < Bsz) {
            float sres = fc_b[0];
            #pragma unroll 10
            for (int j = 0; j < Hd; j++) sres += hbuf[tid][j] * fc_w[j];
            out[be] = sres;
        }
    }
}

extern "C" void kernel_launch(void* const* d_in, const int* in_sizes, int n_in,
                              void* d_out, int out_size)
{
    const float* x     = (const float*)d_in[0];  // [B,T,1]
    const float* w_ih0 = (const float*)d_in[1];  // [200,1]
    const float* w_hh0 = (const float*)d_in[2];  // [200,50]
    const float* b0    = (const float*)d_in[3];  // [200]
    const float* w_ih  = (const float*)d_in[4];  // [4,200,50]
    const float* w_hh  = (const float*)d_in[5];  // [4,200,50]
    const float* b     = (const float*)d_in[6];  // [4,200]
    const float* fc_w  = (const float*)d_in[7];  // [1,50]
    const float* fc_b  = (const float*)d_in[8];  // [1]
    float* out = (float*)d_out;

    float *ysA = nullptr, *ysB = nullptr;
    cudaGetSymbolAddress((void**)&ysA, g_ysA);
    cudaGetSymbolAddress((void**)&ysB, g_ysB);

    // Layer 0
    xg0_kernel<<<TBtot / 32, 200>>>(x, w_ih0, b0);
    rec_kernel<<<RGRID, RNT>>>(w_hh0, ysA, nullptr, nullptr, nullptr);

    // Layers 1..3
    const float* src = ysA;
    float* dst = ysB;
    for (int l = 0; l < 3; l++) {
        xgemm_kernel<<<148, RNT>>>(src, w_ih + (size_t)l * G4 * Hd, b + (size_t)l * G4);
        rec_kernel<<<RGRID, RNT>>>(w_hh + (size_t)l * G4 * Hd, dst, nullptr, nullptr, nullptr);
        const float* tmp = dst; dst = (float*)src; src = tmp;
    }

    // Layer 4: fused FC head
    xgemm_kernel<<<148, RNT>>>(src, w_ih + (size_t)3 * G4 * Hd, b + (size_t)3 * G4);
    rec_kernel<<<RGRID, RNT>>>(w_hh + (size_t)3 * G4 * Hd, nullptr, fc_w, fc_b, out);
}

// round 16
// speedup vs baseline: 1.1118x; 1.1118x over previous
#include <cuda_runtime.h>
#include <cstddef>

#define Hd    50
#define WP    52          // staged row stride (floats)
#define G4    200
#define Bsz   4096
#define Tt    256
#define TBtot (Tt*Bsz)    // 1048576
#define CHK   24          // xgemm chunk (elements)
#define NCHK  43691       // ceil(TBtot/24)
#define TBP   ((size_t)NCHK * CHK)   // 1048584 padded tb extent
#define RNT   384         // rec threads (12 warps = 3 groups x 4 warps)
#define EPG   10          // rec: elements per group
#define EPCTA 30          // rec: elements per CTA (3 groups)
#define RGRID ((Bsz + EPCTA - 1) / EPCTA)   // 137 CTAs

typedef unsigned long long ull;

// Inter-layer activations [tb][50] + input-side preacts [tb][200], padded to TBP
__device__ float g_ysA[TBP * Hd];
__device__ float g_ysB[TBP * Hd];
__device__ float g_xg[TBP * 200];

__device__ __forceinline__ ull ffma2(ull a, ull b, ull c) {
    ull d;
    asm("fma.rn.f32x2 %0, %1, %2, %3;" : "=l"(d) : "l"(a), "l"(b), "l"(c));
    return d;
}
__device__ __forceinline__ float f2sum(ull v) {
    float lo, hi;
    asm("mov.b64 {%0, %1}, %2;" : "=f"(lo), "=f"(hi) : "l"(v));
    return lo + hi;
}
__device__ __forceinline__ float sigf(float x) {
    return __fdividef(1.0f, 1.0f + __expf(-x));
}
__device__ __forceinline__ float tanhf_fast(float x) {
    return 1.0f - __fdividef(2.0f, __expf(2.0f * x) + 1.0f);
}

// ---------------- Phase A, layer 0: XG = x * w_ih0^T + b0 (rank-1) -------------
__global__ __launch_bounds__(200) void xg0_kernel(const float* __restrict__ x,
                                                  const float* __restrict__ w0,
                                                  const float* __restrict__ b0)
{
    __shared__ float xs[32];
    const int cid = blockIdx.x;
    const int t   = cid >> 7;
    const int bb  = (cid & 127) << 5;
    const int row = threadIdx.x;           // 0..199
    if (row < 32) xs[row] = x[(size_t)(bb + row) * Tt + t];
    const float wv = w0[row], bv = b0[row];
    __syncthreads();
    float* base = g_xg + ((size_t)t * Bsz + bb) * 200 + row;
    #pragma unroll 8
    for (int el = 0; el < 32; el++)
        base[(size_t)el * 200] = xs[el] * wv + bv;
}

// ---------------- Phase A, layers 1..4: XG = ys * W_ih^T + bias ----------------
// 384 threads = 3 teams x 4 warps; warp owns TWO row-sets (rA=50wg+lane, rB=rA+25,
// 100 weight regs). Team tm handles 8 els of the 24-el chunk; h loaded once per
// el, reused for both row-sets -> broadcast LDS halved. Warp el-order rotated
// by wg*2 to break LDS/FMA convoys.
__global__ __launch_bounds__(RNT, 1) void xgemm_kernel(const float* __restrict__ ys,
                                                       const float* __restrict__ w,
                                                       const float* __restrict__ bias)
{
    __shared__ float sin[CHK * WP];
    const int tid  = threadIdx.x;
    const int wid  = tid >> 5;
    const int lane = tid & 31;
    const int tm   = wid >> 2;          // team 0..2
    const int wg   = wid & 3;           // warp-in-team 0..3
    const bool act = lane < 25;
    const int rA   = 50 * wg + (act ? lane : 24);
    const int rB   = rA + 25;
    const int eb   = tm * 8;            // team's el base

    ull wregA[25], wregB[25];
    {
        const ull* wpA = (const ull*)(w + rA * Hd);
        const ull* wpB = (const ull*)(w + rB * Hd);
        #pragma unroll
        for (int q = 0; q < 25; q++) { wregA[q] = wpA[q]; wregB[q] = wpB[q]; }
    }
    const float brA = bias[rA], brB = bias[rB];

    int c = blockIdx.x;
    float pf[4];
    #pragma unroll
    for (int k = 0; k < 4; k++) {
        int idx = tid + RNT * k;
        pf[k] = (idx < CHK * Hd) ? ys[(size_t)c * (CHK * Hd) + idx] : 0.0f;
    }

    for (; c < NCHK; c += gridDim.x) {
        __syncthreads();
        #pragma unroll
        for (int k = 0; k < 4; k++) {
            int idx = tid + RNT * k;
            if (idx < CHK * Hd) { int el = idx / Hd, j = idx - el * Hd; sin[el * WP + j] = pf[k]; }
        }
        __syncthreads();
        int cn = c + gridDim.x;
        if (cn < NCHK) {
            #pragma unroll
            for (int k = 0; k < 4; k++) {
                int idx = tid + RNT * k;
                if (idx < CHK * Hd) pf[k] = ys[(size_t)cn * (CHK * Hd) + idx];
            }
        }
        float* obase = g_xg + ((size_t)c * CHK + eb) * 200;

        #pragma unroll
        for (int k = 0; k < 8; k++) {
            const int el = (k + wg * 2) & 7;   // rotated visit order
            const ulonglong2* hp = (const ulonglong2*)(sin + (eb + el) * WP);
            ulonglong2 hv[13];
            #pragma unroll
            for (int q = 0; q < 13; q++) hv[q] = hp[q];
            ull accA = 0ull, accB = 0ull;
            #pragma unroll
            for (int q = 0; q < 12; q++) {
                accA = ffma2(wregA[2*q],   hv[q].x, accA);
                accA = ffma2(wregA[2*q+1], hv[q].y, accA);
                accB = ffma2(wregB[2*q],   hv[q].x, accB);
                accB = ffma2(wregB[2*q+1], hv[q].y, accB);
            }
            accA = ffma2(wregA[24], hv[12].x, accA);   // floats 48,49 (pads excluded)
            accB = ffma2(wregB[24], hv[12].x, accB);
            if (act) {
                obase[(size_t)el * 200 + rA] = f2sum(accA) + brA;
                obase[(size_t)el * 200 + rB] = f2sum(accB) + brB;
            }
        }
    }
}

// ---------------- Phase B: recurrence, weights register-stationary -------------
// 12 warps = 3 groups x 4 warps; group owns EPG=10 batch elements (CTA=30).
// Warp owns TWO row-sets: lane<25 holds rows 50wg+lane and 50wg+25+lane (100
// weight regs). h loaded to registers ONCE per element, reused for both sets.
// Sequential el order (R14-proven; rotation regressed in R15).
__global__ __launch_bounds__(RNT, 1)
void rec_kernel(const float* __restrict__ w_hh,
                float* __restrict__ ys_out,
                const float* __restrict__ fc_w,
                const float* __restrict__ fc_b,
                float* __restrict__ out)
{
    __shared__ float hbuf[EPCTA][52];    // [ei][u], cols 50,51 stay 0
    __shared__ float pbuf[EPCTA][208];   // [ei][row]

    const int tid  = threadIdx.x;
    const int wid  = tid >> 5;
    const int lane = tid & 31;
    const int g    = wid >> 2;        // group 0..2
    const int wg   = wid & 3;         // warp-in-group 0..3
    const int tidg = tid & 127;       // thread-in-group (128 per group)
    const int barid = 1 + g;

    const int bG = blockIdx.x * EPCTA + g * EPG;   // group's first element

    // ---- weights: lane<25 owns rows rA=50wg+lane and rB=rA+25 ----
    const bool wact = lane < 25;
    const int rA = 50 * wg + (wact ? lane : 24);
    const int rB = rA + 25;
    ull wregA[25], wregB[25];
    {
        const ull* wpA = (const ull*)(w_hh + rA * Hd);
        const ull* wpB = (const ull*)(w_hh + rB * Hd);
        #pragma unroll
        for (int q = 0; q < 25; q++) { wregA[q] = wpA[q]; wregB[q] = wpB[q]; }
    }

    // ---- gates items: 4 fixed (el,u) per thread (500 items over 128 threads) ----
    int elk[4], uk[4];
    bool actk[4], gbl[4];
    #pragma unroll
    for (int k = 0; k < 4; k++) {
        int item = tidg + 128 * k;
        actk[k] = item < EPG * 50;
        int it = actk[k] ? item : (EPG * 50 - 1);
        elk[k] = it / 50;
        uk[k]  = it - elk[k] * 50;
        gbl[k] = actk[k] && (bG + elk[k] < Bsz);
    }
    float c[4] = {0.f, 0.f, 0.f, 0.f};

    // ---- zero hbuf ----
    for (int i = tid; i < EPCTA * 52; i += RNT) ((float*)hbuf)[i] = 0.0f;
    __syncthreads();

    for (int t = 0; t < Tt; t++) {
        const size_t tb = (size_t)t * Bsz;

        // ---- XG prefetch for my gate items (guarded, hidden under dot) ----
        float xgr[4][4];
        #pragma unroll
        for (int k = 0; k < 4; k++) {
            if (gbl[k]) {
                const float* xp = g_xg + (tb + bG + elk[k]) * 200 + uk[k];
                #pragma unroll
                for (int gg = 0; gg < 4; gg++) xgr[k][gg] = xp[gg * 50];
            } else {
                #pragma unroll
                for (int gg = 0; gg < 4; gg++) xgr[k][gg] = 0.0f;
            }
        }

        // ---- dot: stream EPG elements; h loaded once, used for BOTH row-sets ----
        #pragma unroll 2
        for (int el = 0; el < EPG; el++) {
            const int ei = g * EPG + el;
            ulonglong2 hv[13];
            {
                const ulonglong2* hp = (const ulonglong2*)hbuf[ei];
                #pragma unroll
                for (int q = 0; q < 13; q++) hv[q] = hp[q];
            }
            ull accA = 0ull, accB = 0ull;
            #pragma unroll
            for (int q = 0; q < 12; q++) {
                accA = ffma2(wregA[2*q],   hv[q].x, accA);
                accA = ffma2(wregA[2*q+1], hv[q].y, accA);
                accB = ffma2(wregB[2*q],   hv[q].x, accB);
                accB = ffma2(wregB[2*q+1], hv[q].y, accB);
            }
            accA = ffma2(wregA[24], hv[12].x, accA);
            accB = ffma2(wregB[24], hv[12].x, accB);
            if (wact) {
                pbuf[ei][rA] = f2sum(accA);
                pbuf[ei][rB] = f2sum(accB);
            }
        }

        asm volatile("bar.sync %0, %1;" :: "r"(barid), "r"(128) : "memory");

        // ---- gates: 500 items over 128 group threads ----
        #pragma unroll
        for (int k = 0; k < 4; k++) {
            if (actk[k]) {
                const int ei = g * EPG + elk[k];
                const int u  = uk[k];
                float pi = pbuf[ei][u]        + xgr[k][0];
                float pf = pbuf[ei][50 + u]   + xgr[k][1];
                float pg = pbuf[ei][100 + u]  + xgr[k][2];
                float po = pbuf[ei][150 + u]  + xgr[k][3];
                c[k] = sigf(pf) * c[k] + sigf(pi) * tanhf_fast(pg);
                float hv = sigf(po) * tanhf_fast(c[k]);
                hbuf[ei][u] = hv;
                if (gbl[k] && ys_out) ys_out[(tb + bG + elk[k]) * Hd + u] = hv;
            }
        }

        asm volatile("bar.sync %0, %1;" :: "r"(barid), "r"(128) : "memory");
    }

    // ---- FC head (last layer only) ----
    if (out != nullptr) {
        __syncthreads();
        int be = blockIdx.x * EPCTA + tid;
        if (tid < EPCTA && be < Bsz) {
            float sres = fc_b[0];
            #pragma unroll 10
            for (int j = 0; j < Hd; j++) sres += hbuf[tid][j] * fc_w[j];
            out[be] = sres;
        }
    }
}

extern "C" void kernel_launch(void* const* d_in, const int* in_sizes, int n_in,
                              void* d_out, int out_size)
{
    const float* x     = (const float*)d_in[0];  // [B,T,1]
    const float* w_ih0 = (const float*)d_in[1];  // [200,1]
    const float* w_hh0 = (const float*)d_in[2];  // [200,50]
    const float* b0    = (const float*)d_in[3];  // [200]
    const float* w_ih  = (const float*)d_in[4];  // [4,200,50]
    const float* w_hh  = (const float*)d_in[5];  // [4,200,50]
    const float* b     = (const float*)d_in[6];  // [4,200]
    const float* fc_w  = (const float*)d_in[7];  // [1,50]
    const float* fc_b  = (const float*)d_in[8];  // [1]
    float* out = (float*)d_out;

    float *ysA = nullptr, *ysB = nullptr;
    cudaGetSymbolAddress((void**)&ysA, g_ysA);
    cudaGetSymbolAddress((void**)&ysB, g_ysB);

    // Layer 0
    xg0_kernel<<<TBtot / 32, 200>>>(x, w_ih0, b0);
    rec_kernel<<<RGRID, RNT>>>(w_hh0, ysA, nullptr, nullptr, nullptr);

    // Layers 1..3
    const float* src = ysA;
    float* dst = ysB;
    for (int l = 0; l < 3; l++) {
        xgemm_kernel<<<148, RNT>>>(src, w_ih + (size_t)l * G4 * Hd, b + (size_t)l * G4);
        rec_kernel<<<RGRID, RNT>>>(w_hh + (size_t)l * G4 * Hd, dst, nullptr, nullptr, nullptr);
        const float* tmp = dst; dst = (float*)src; src = tmp;
    }

    // Layer 4: fused FC head
    xgemm_kernel<<<148, RNT>>>(src, w_ih + (size_t)3 * G4 * Hd, b + (size_t)3 * G4);
    rec_kernel<<<RGRID, RNT>>>(w_hh + (size_t)3 * G4 * Hd, nullptr, fc_w, fc_b, out);
}